// round 2
// baseline (speedup 1.0000x reference)
#include <cuda_runtime.h>
#include <cstdint>
#include <cstddef>
#include <math.h>

// Problem dims (fixed by the reference)
#define SS   128      // seq len
#define BBT  128      // batch
#define EE   256      // embed
#define HHD  256      // hidden
#define G4   1024     // 4*H
#define NSEQ 3
#define NSTREAM 768   // 3 seqs * 2 dirs * 128 batch rows
#define D2H  512      // 2*H

// ---------------- scratch (device globals; no cudaMalloc allowed) ------------
__device__ float g_Gf  [(size_t)NSEQ*SS*BBT*G4];        // 201 MB  [seq][s][b][4H]
__device__ float g_Gb  [(size_t)NSEQ*SS*BBT*G4];        // 201 MB
__device__ float g_out [(size_t)NSEQ*BBT*SS*D2H];       // 101 MB  [seq][b][s][2H]
__device__ float g_h   [2*NSTREAM*HHD];                 // double-buffered h state
__device__ float g_c   [NSTREAM*HHD];                   // cell state
__device__ float g_Ct  [(size_t)BBT*SS*D2H];            // tanh(S1(C0))
__device__ float g_Hm  [(size_t)BBT*SS*SS];
__device__ float g_AQ  [(size_t)BBT*SS*SS];
__device__ float g_AC  [(size_t)BBT*SS*SS];

__device__ __forceinline__ float sigf(float x) { return 1.0f / (1.0f + expf(-x)); }

// ---------------- init states from input hidden/cell -------------------------
__global__ void init_state(const float* hQ, const float* cQ, const float* hC, const float* cC,
                           const float* hC2, const float* cC2) {
    int i = blockIdx.x * 256 + threadIdx.x;             // 768*256
    if (i >= NSTREAM * HHD) return;
    int m = i >> 8, k = i & 255;
    int half = m / 384;                                 // 0 fwd, 1 bwd
    int mm = m % 384;
    int seq = mm >> 7, bb = mm & 127;
    const float* hsrc = (seq == 0) ? hQ : (seq == 1) ? hC : hC2;
    const float* csrc = (seq == 0) ? cQ : (seq == 1) ? cC : cC2;
    g_h[i] = hsrc[(half * BBT + bb) * HHD + k];         // into buffer 0
    g_c[i] = csrc[(half * BBT + bb) * HHD + k];
}

// ---------------- fused embed-gather + input projection ----------------------
// G[row][:] = emb[tok(row)] @ W^T + b1 + b2.  Rows: seq*16384 + s*128 + b.
// Tile 128x128, BK=16, 256 threads, 8x8 per thread. K = EE = 256, N = G4 = 1024.
__global__ void __launch_bounds__(256) gemm_inproj(
    const int* __restrict__ iQ, const int* __restrict__ iC, const int* __restrict__ iC2,
    const float* __restrict__ emb,
    const float* __restrict__ W, const float* __restrict__ b1, const float* __restrict__ b2,
    float* __restrict__ G) {
    int m0 = blockIdx.y * 128, n0 = blockIdx.x * 128;
    __shared__ float As[16][136];
    __shared__ float Ws[16][136];
    __shared__ int   toks[128];
    int tid = threadIdx.x;
    if (tid < 128) {
        int row = m0 + tid;
        int seq = row >> 14, rem = row & 16383;
        const int* idx = (seq == 0) ? iQ : (seq == 1) ? iC : iC2;
        toks[tid] = idx[rem];
    }
    __syncthreads();
    int tx = tid & 15, ty = tid >> 4;
    float acc[8][8] = {};
    for (int k0 = 0; k0 < EE; k0 += 16) {
#pragma unroll
        for (int i = 0; i < 2; i++) {                   // A tile: 512 float4
            int q = i * 256 + tid;
            int r = q >> 2, kq = q & 3;
            float4 v = *(const float4*)&emb[(size_t)toks[r] * EE + k0 + kq * 4];
            As[kq * 4 + 0][r] = v.x; As[kq * 4 + 1][r] = v.y;
            As[kq * 4 + 2][r] = v.z; As[kq * 4 + 3][r] = v.w;
        }
#pragma unroll
        for (int i = 0; i < 2; i++) {                   // W tile: 512 float4
            int q = i * 256 + tid;
            int r = q >> 2, kq = q & 3;
            float4 v = *(const float4*)&W[(size_t)(n0 + r) * EE + k0 + kq * 4];
            Ws[kq * 4 + 0][r] = v.x; Ws[kq * 4 + 1][r] = v.y;
            Ws[kq * 4 + 2][r] = v.z; Ws[kq * 4 + 3][r] = v.w;
        }
        __syncthreads();
#pragma unroll
        for (int kk = 0; kk < 16; kk++) {
            float a[8], w[8];
#pragma unroll
            for (int i = 0; i < 8; i++) a[i] = As[kk][ty * 8 + i];
#pragma unroll
            for (int j = 0; j < 8; j++) w[j] = Ws[kk][tx * 8 + j];
#pragma unroll
            for (int i = 0; i < 8; i++)
#pragma unroll
                for (int j = 0; j < 8; j++) acc[i][j] += a[i] * w[j];
        }
        __syncthreads();
    }
    int colb = n0 + tx * 8;
    float bv[8];
#pragma unroll
    for (int j = 0; j < 8; j++) bv[j] = b1[colb + j] + b2[colb + j];
#pragma unroll
    for (int i = 0; i < 8; i++) {
        float* dst = &G[(size_t)(m0 + ty * 8 + i) * G4 + colb];
        float4 o0, o1;
        o0.x = acc[i][0] + bv[0]; o0.y = acc[i][1] + bv[1];
        o0.z = acc[i][2] + bv[2]; o0.w = acc[i][3] + bv[3];
        o1.x = acc[i][4] + bv[4]; o1.y = acc[i][5] + bv[5];
        o1.z = acc[i][6] + bv[6]; o1.w = acc[i][7] + bv[7];
        *(float4*)dst = o0; *(float4*)(dst + 4) = o1;
    }
}

// ---------------- generic GEMM: C = act(A @ W^T + b1), batched over z --------
// A: [M,K] rm, W: [N,K] rm, C: [M,N] rm. 128x128 tile, BK=16, 256 thr, 8x8/thr.
// M,N multiples of 128, K of 16 (true at all call sites).
template <int ACT>
__global__ void __launch_bounds__(256) gemm_atb(
    const float* __restrict__ Ag, size_t sA,
    const float* __restrict__ Wg, size_t sW,
    const float* __restrict__ b1,
    float* __restrict__ Cg, size_t sC, int N, int K) {
    const float* A = Ag + (size_t)blockIdx.z * sA;
    const float* W = Wg + (size_t)blockIdx.z * sW;
    float*       C = Cg + (size_t)blockIdx.z * sC;
    int m0 = blockIdx.y * 128, n0 = blockIdx.x * 128;
    __shared__ float As[16][136];
    __shared__ float Ws[16][136];
    int tid = threadIdx.x;
    int tx = tid & 15, ty = tid >> 4;
    float acc[8][8] = {};
    for (int k0 = 0; k0 < K; k0 += 16) {
#pragma unroll
        for (int i = 0; i < 2; i++) {
            int q = i * 256 + tid;
            int r = q >> 2, kq = q & 3;
            float4 v = *(const float4*)&A[(size_t)(m0 + r) * K + k0 + kq * 4];
            As[kq * 4 + 0][r] = v.x; As[kq * 4 + 1][r] = v.y;
            As[kq * 4 + 2][r] = v.z; As[kq * 4 + 3][r] = v.w;
        }
#pragma unroll
        for (int i = 0; i < 2; i++) {
            int q = i * 256 + tid;
            int r = q >> 2, kq = q & 3;
            float4 v = *(const float4*)&W[(size_t)(n0 + r) * K + k0 + kq * 4];
            Ws[kq * 4 + 0][r] = v.x; Ws[kq * 4 + 1][r] = v.y;
            Ws[kq * 4 + 2][r] = v.z; Ws[kq * 4 + 3][r] = v.w;
        }
        __syncthreads();
#pragma unroll
        for (int kk = 0; kk < 16; kk++) {
            float a[8], w[8];
#pragma unroll
            for (int i = 0; i < 8; i++) a[i] = As[kk][ty * 8 + i];
#pragma unroll
            for (int j = 0; j < 8; j++) w[j] = Ws[kk][tx * 8 + j];
#pragma unroll
            for (int i = 0; i < 8; i++)
#pragma unroll
                for (int j = 0; j < 8; j++) acc[i][j] += a[i] * w[j];
        }
        __syncthreads();
    }
    int colb = n0 + tx * 8;
    float bv[8];
#pragma unroll
    for (int j = 0; j < 8; j++) bv[j] = b1 ? b1[colb + j] : 0.f;
#pragma unroll
    for (int i = 0; i < 8; i++) {
        float* dst = &C[(size_t)(m0 + ty * 8 + i) * N + colb];
        float o[8];
#pragma unroll
        for (int j = 0; j < 8; j++) {
            o[j] = acc[i][j] + bv[j];
            if (ACT == 1) o[j] = tanhf(o[j]);
        }
        float4 o0 = {o[0], o[1], o[2], o[3]}, o1 = {o[4], o[5], o[6], o[7]};
        *(float4*)dst = o0; *(float4*)(dst + 4) = o1;
    }
}

// ---------------- generic GEMM: C = A @ B, batched over z --------------------
// A: [M,K] rm, B: [K,N] rm. BM=64, BN=64, BK=16, 256 thr, 4x4/thr.
__global__ void __launch_bounds__(256) gemm_ab(
    const float* __restrict__ Ag, size_t sA,
    const float* __restrict__ Bg, size_t sB,
    float* __restrict__ Cg, size_t sC, int N, int K) {
    const float* A = Ag + (size_t)blockIdx.z * sA;
    const float* B = Bg + (size_t)blockIdx.z * sB;
    float*       C = Cg + (size_t)blockIdx.z * sC;
    int m0 = blockIdx.y * 64, n0 = blockIdx.x * 64;
    __shared__ float As[16][68];
    __shared__ float Bs[16][68];
    int tid = threadIdx.x;
    int tx = tid & 15, ty = tid >> 4;
    float acc[4][4] = {};
    for (int k0 = 0; k0 < K; k0 += 16) {
        {   // A: 256 float4, transpose into As
            int r = tid >> 2, kq = tid & 3;
            float4 v = *(const float4*)&A[(size_t)(m0 + r) * K + k0 + kq * 4];
            As[kq * 4 + 0][r] = v.x; As[kq * 4 + 1][r] = v.y;
            As[kq * 4 + 2][r] = v.z; As[kq * 4 + 3][r] = v.w;
        }
        {   // B: 256 float4, direct
            int kr = tid >> 4, nq = tid & 15;
            float4 v = *(const float4*)&B[(size_t)(k0 + kr) * N + n0 + nq * 4];
            Bs[kr][nq * 4 + 0] = v.x; Bs[kr][nq * 4 + 1] = v.y;
            Bs[kr][nq * 4 + 2] = v.z; Bs[kr][nq * 4 + 3] = v.w;
        }
        __syncthreads();
#pragma unroll
        for (int kk = 0; kk < 16; kk++) {
            float a[4], b[4];
#pragma unroll
            for (int i = 0; i < 4; i++) a[i] = As[kk][ty * 4 + i];
#pragma unroll
            for (int j = 0; j < 4; j++) b[j] = Bs[kk][tx * 4 + j];
#pragma unroll
            for (int i = 0; i < 4; i++)
#pragma unroll
                for (int j = 0; j < 4; j++) acc[i][j] += a[i] * b[j];
        }
        __syncthreads();
    }
#pragma unroll
    for (int i = 0; i < 4; i++) {
        float4 o; o.x = acc[i][0]; o.y = acc[i][1]; o.z = acc[i][2]; o.w = acc[i][3];
        *(float4*)&C[(size_t)(m0 + ty * 4 + i) * N + n0 + tx * 4] = o;
    }
}

// ---------------- fused LSTM step -------------------------------------------
// grid (16 hidBlocks, 12 rowBlocks), 256 threads.
// Each CTA: 64 stream-rows x 16 hidden units (=> 64 gate cols), GEMM over K=256,
// + Gx add, gate nonlinearity, c/h update, and output scatter.
__global__ void __launch_bounds__(256) lstm_step(
    const float* __restrict__ h_prev, float* __restrict__ h_next,
    const float* __restrict__ Whh_f, const float* __restrict__ Whh_b, int t) {
    int hb = blockIdx.x, rb = blockIdx.y;
    int m0 = rb * 64, j0 = hb * 16;
    bool bwd = (rb >= 6);
    const float* W = bwd ? Whh_b : Whh_f;
    __shared__ float Hs[16][65];
    __shared__ float Ws[16][65];
    __shared__ float Gt[64][65];
    int tid = threadIdx.x;
    int tx = tid & 15, ty = tid >> 4;
    int lr = tid >> 2, lk = tid & 3;
    int gcW = ((lr >> 4) << 8) + j0 + (lr & 15);        // global gate col for W load row
    const float* wrow = W + (size_t)gcW * HHD;
    const float* hrow = h_prev + (size_t)(m0 + lr) * HHD;
    float acc[4][4] = {};
    for (int k0 = 0; k0 < HHD; k0 += 16) {
        float4 hv = *(const float4*)&hrow[k0 + lk * 4];
        float4 wv = *(const float4*)&wrow[k0 + lk * 4];
        Hs[lk * 4 + 0][lr] = hv.x; Hs[lk * 4 + 1][lr] = hv.y;
        Hs[lk * 4 + 2][lr] = hv.z; Hs[lk * 4 + 3][lr] = hv.w;
        Ws[lk * 4 + 0][lr] = wv.x; Ws[lk * 4 + 1][lr] = wv.y;
        Ws[lk * 4 + 2][lr] = wv.z; Ws[lk * 4 + 3][lr] = wv.w;
        __syncthreads();
#pragma unroll
        for (int kk = 0; kk < 16; kk++) {
            float a[4], w[4];
#pragma unroll
            for (int i = 0; i < 4; i++) a[i] = Hs[kk][ty * 4 + i];
#pragma unroll
            for (int j = 0; j < 4; j++) w[j] = Ws[kk][tx * 4 + j];
#pragma unroll
            for (int i = 0; i < 4; i++)
#pragma unroll
                for (int j = 0; j < 4; j++) acc[i][j] += a[i] * w[j];
        }
        __syncthreads();
    }
    // add precomputed input gates (+bias already folded in), stage to smem
#pragma unroll
    for (int i = 0; i < 4; i++) {
        int mg = m0 + ty * 4 + i;
        const float* gptr;
        size_t base;
        if (!bwd) {
            int seq = mg >> 7, bb = mg & 127;
            base = (((size_t)seq * SS + t) * BBT + bb) * G4;
            gptr = g_Gf;
        } else {
            int mm = mg - 384;
            int seq = mm >> 7, bb = mm & 127;
            base = (((size_t)seq * SS + (SS - 1 - t)) * BBT + bb) * G4;
            gptr = g_Gb;
        }
#pragma unroll
        for (int j = 0; j < 4; j++) {
            int c  = tx * 4 + j;
            int gc = ((c >> 4) << 8) + j0 + (c & 15);
            Gt[ty * 4 + i][c] = acc[i][j] + gptr[base + gc];
        }
    }
    __syncthreads();
    // pointwise: 64 rows x 16 units, 4 per thread
#pragma unroll
    for (int q = 0; q < 4; q++) {
        int p = tid * 4 + q;
        int r = p >> 4, u = p & 15;
        float gi = Gt[r][u], gf = Gt[r][16 + u], gg = Gt[r][32 + u], go = Gt[r][48 + u];
        int mg = m0 + r, unit = j0 + u;
        size_t si = (size_t)mg * HHD + unit;
        float cold = g_c[si];
        float cn = sigf(gf) * cold + sigf(gi) * tanhf(gg);
        float hn = sigf(go) * tanhf(cn);
        g_c[si] = cn;
        h_next[si] = hn;
        int seq, bb, time, coff;
        if (!bwd) { seq = mg >> 7; bb = mg & 127; time = t; coff = unit; }
        else { int mm = mg - 384; seq = mm >> 7; bb = mm & 127; time = SS - 1 - t; coff = HHD + unit; }
        g_out[(((size_t)seq * BBT + bb) * SS + time) * D2H + coff] = hn;
    }
}

// ---------------- fused row+col softmax of Hm --------------------------------
// AQ[i][j] = softmax_j(Hm[i][j]);  AC[t][s] = exp(Hm[s][t])/sum_s' exp(Hm[s'][t]).
// One CTA per batch; thr 0..127 rows, 128..255 cols.
__global__ void __launch_bounds__(256) attn_softmax(const float* __restrict__ Hm,
                                                    float* __restrict__ AQ,
                                                    float* __restrict__ AC) {
    int b = blockIdx.x;
    const float* H = Hm + (size_t)b * SS * SS;
    int tid = threadIdx.x;
    if (tid < 128) {
        const float* row = H + tid * SS;
        float mx = -1e30f;
#pragma unroll 8
        for (int j = 0; j < SS; j++) mx = fmaxf(mx, row[j]);
        float s = 0.f;
#pragma unroll 8
        for (int j = 0; j < SS; j++) s += expf(row[j] - mx);
        float inv = 1.f / s;
        float* out = AQ + (size_t)b * SS * SS + tid * SS;
#pragma unroll 8
        for (int j = 0; j < SS; j++) out[j] = expf(row[j] - mx) * inv;
    } else {
        int c = tid - 128;
        float mx = -1e30f;
#pragma unroll 8
        for (int j = 0; j < SS; j++) mx = fmaxf(mx, H[j * SS + c]);
        float s = 0.f;
#pragma unroll 8
        for (int j = 0; j < SS; j++) s += expf(H[j * SS + c] - mx);
        float inv = 1.f / s;
        float* out = AC + (size_t)b * SS * SS + c * SS;
#pragma unroll 8
        for (int j = 0; j < SS; j++) out[j] = expf(H[j * SS + c] - mx) * inv;
    }
}

// ---------------- launcher ---------------------------------------------------
extern "C" void kernel_launch(void* const* d_in, const int* in_sizes, int n_in,
                              void* d_out, int out_size) {
    (void)in_sizes; (void)out_size;
    int base = n_in - 20;   // skip batch_size if present
    const int*   iQ    = (const int*)d_in[base + 0];
    const int*   iC    = (const int*)d_in[base + 1];
    const int*   iC2   = (const int*)d_in[base + 2];
    const float* hQ    = (const float*)d_in[base + 3];
    const float* cQ    = (const float*)d_in[base + 4];
    const float* hC    = (const float*)d_in[base + 5];
    const float* cC    = (const float*)d_in[base + 6];
    const float* hC2   = (const float*)d_in[base + 7];
    const float* cC2   = (const float*)d_in[base + 8];
    const float* emb   = (const float*)d_in[base + 9];
    const float* Wih_f = (const float*)d_in[base + 10];
    const float* Whh_f = (const float*)d_in[base + 11];
    const float* bih_f = (const float*)d_in[base + 12];
    const float* bhh_f = (const float*)d_in[base + 13];
    const float* Wih_b = (const float*)d_in[base + 14];
    const float* Whh_b = (const float*)d_in[base + 15];
    const float* bih_b = (const float*)d_in[base + 16];
    const float* bhh_b = (const float*)d_in[base + 17];
    const float* S1_W  = (const float*)d_in[base + 18];
    const float* S1_b  = (const float*)d_in[base + 19];
    float* dout = (float*)d_out;

    float *pGf, *pGb, *pOut, *pH, *pCt, *pHm, *pAQ, *pAC;
    cudaGetSymbolAddress((void**)&pGf, g_Gf);
    cudaGetSymbolAddress((void**)&pGb, g_Gb);
    cudaGetSymbolAddress((void**)&pOut, g_out);
    cudaGetSymbolAddress((void**)&pH,  g_h);
    cudaGetSymbolAddress((void**)&pCt, g_Ct);
    cudaGetSymbolAddress((void**)&pHm, g_Hm);
    cudaGetSymbolAddress((void**)&pAQ, g_AQ);
    cudaGetSymbolAddress((void**)&pAC, g_AC);

    // 1. fused embedding gather + input projections (both biases folded in)
    {
        dim3 grid(G4 / 128, (NSEQ * SS * BBT) / 128);
        gemm_inproj<<<grid, 256>>>(iQ, iC, iC2, emb, Wih_f, bih_f, bhh_f, pGf);
        gemm_inproj<<<grid, 256>>>(iQ, iC, iC2, emb, Wih_b, bih_b, bhh_b, pGb);
    }

    // 2. init states
    init_state<<<(NSTREAM * HHD + 255) / 256, 256>>>(hQ, cQ, hC, cC, hC2, cC2);

    // 3. recurrence: 128 fused steps, h double-buffered
    float* h0 = pH;
    float* h1 = pH + NSTREAM * HHD;
    for (int t = 0; t < SS; t++) {
        float* prev = (t & 1) ? h1 : h0;
        float* next = (t & 1) ? h0 : h1;
        lstm_step<<<dim3(16, 12), 256>>>(prev, next, Whh_f, Whh_b, t);
    }

    // 4. two attention blocks; MQ/MC land directly in d_out
    const float* pQ = pOut;  // out_q = seq 0, [B][S][2H]
    for (int a = 0; a < 2; a++) {
        const float* C0 = pOut + (size_t)(a + 1) * BBT * SS * D2H;   // out_c / out_c2
        // Ct = tanh(C0 @ S1_W^T + S1_b)
        gemm_atb<1><<<dim3(D2H / 128, (BBT * SS) / 128), 256>>>(
            C0, 0, S1_W, 0, S1_b, pCt, 0, D2H, D2H);
        // Hm_b = Q_b @ Ct_b^T   (batched over z)
        gemm_atb<0><<<dim3(1, 1, BBT), 256>>>(
            pQ, (size_t)SS * D2H, pCt, (size_t)SS * D2H, nullptr,
            pHm, (size_t)SS * SS, SS, D2H);
        // AQ / AC
        attn_softmax<<<BBT, 256>>>(pHm, pAQ, pAC);
        // MQ = AQ @ Q  -> out section 2a ;  MC = AC @ MQ -> out section 2a+1
        float* oMQ = dout + (size_t)(2 * a)     * BBT * SS * D2H;
        float* oMC = dout + (size_t)(2 * a + 1) * BBT * SS * D2H;
        gemm_ab<<<dim3(D2H / 64, SS / 64, BBT), 256>>>(
            pAQ, (size_t)SS * SS, pQ, (size_t)SS * D2H, oMQ, (size_t)SS * D2H, D2H, SS);
        gemm_ab<<<dim3(D2H / 64, SS / 64, BBT), 256>>>(
            pAC, (size_t)SS * SS, oMQ, (size_t)SS * D2H, oMC, (size_t)SS * D2H, D2H, SS);
    }
}